// round 3
// baseline (speedup 1.0000x reference)
#include <cuda_runtime.h>

// Problem constants (fixed shapes per reference)
#define B_SZ 32768
#define D_SZ 256
#define K_SZ 1024

// GEMM tiling
#define BM 128
#define BN 128
#define BKD 16
#define TM 8
#define TN 8
#define NTHREADS 256   // (BM/TM)*(BN/TN) = 16*16

// Scratch: reciprocal squared-norms of codebook rows
__device__ float g_inv_norms[K_SZ];

// ---------------------------------------------------------------------------
// Kernel 1: inv_norms[k] = 1 / sum_d C[k,d]^2   (one warp per code)
// ---------------------------------------------------------------------------
__global__ void vq_norms_kernel(const float* __restrict__ C) {
    int k = blockIdx.x;
    int lane = threadIdx.x;  // 32 threads
    const float4* row = reinterpret_cast<const float4*>(C + (size_t)k * D_SZ);
    float s = 0.f;
#pragma unroll
    for (int i = 0; i < (D_SZ / 4) / 32; i++) {   // 2 iterations
        float4 v = row[lane + 32 * i];
        s += v.x * v.x + v.y * v.y + v.z * v.z + v.w * v.w;
    }
#pragma unroll
    for (int o = 16; o > 0; o >>= 1) s += __shfl_xor_sync(0xffffffffu, s, o);
    if (lane == 0) g_inv_norms[k] = 1.0f / s;
}

// ---------------------------------------------------------------------------
// Kernel 2: fused SGEMM (E @ C^T) + running argmax(dot^2 * inv_norm) + gather
// One block handles BM=128 embedding rows against all K=1024 codes.
// ---------------------------------------------------------------------------
__global__ __launch_bounds__(NTHREADS) void vq_main_kernel(
    const float* __restrict__ E,   // [B, D]
    const float* __restrict__ C,   // [K, D]
    float* __restrict__ z_out,     // [B, D]
    float* __restrict__ idx_out,   // [B] (as float)
    int write_idx)
{
    __shared__ float As[BKD][BM];   // 8 KB
    __shared__ float Bs[BKD][BN];   // 8 KB
    // cross-thread argmax reduction storage (per row, 16 candidates)
    __shared__ float s_score[BM][16];  // 8 KB
    __shared__ int   s_bidx[BM][16];   // 8 KB
    __shared__ float s_bdot[BM][16];   // 8 KB
    __shared__ float s_alpha[BM];
    __shared__ int   s_final[BM];

    const int tid = threadIdx.x;
    const int tx = tid & 15;       // code-tile column group
    const int ty = tid >> 4;       // row group
    const int row0 = blockIdx.x * BM;

    float best_score[TM];
    int   best_idx[TM];
    float best_dot[TM];
#pragma unroll
    for (int i = 0; i < TM; i++) { best_score[i] = -1.0f; best_idx[i] = 0; best_dot[i] = 0.0f; }

    for (int ct = 0; ct < K_SZ / BN; ct++) {          // 8 code tiles
        const int code0 = ct * BN;
        float acc[TM][TN];
#pragma unroll
        for (int i = 0; i < TM; i++)
#pragma unroll
            for (int j = 0; j < TN; j++) acc[i][j] = 0.0f;

        for (int kk = 0; kk < D_SZ; kk += BKD) {      // 16 k-chunks
            // Load A tile (128 rows x 16 cols) transposed into As[k][m]
#pragma unroll
            for (int i = 0; i < 2; i++) {
                int f = tid + NTHREADS * i;           // 0..511 float4 slots
                int r = f >> 2;                       // 0..127
                int c = (f & 3) * 4;                  // 0,4,8,12
                float4 v = *reinterpret_cast<const float4*>(
                    E + (size_t)(row0 + r) * D_SZ + kk + c);
                As[c + 0][r] = v.x; As[c + 1][r] = v.y;
                As[c + 2][r] = v.z; As[c + 3][r] = v.w;
            }
            // Load B tile (128 codes x 16 cols) transposed into Bs[k][n]
#pragma unroll
            for (int i = 0; i < 2; i++) {
                int f = tid + NTHREADS * i;
                int r = f >> 2;
                int c = (f & 3) * 4;
                float4 v = *reinterpret_cast<const float4*>(
                    C + (size_t)(code0 + r) * D_SZ + kk + c);
                Bs[c + 0][r] = v.x; Bs[c + 1][r] = v.y;
                Bs[c + 2][r] = v.z; Bs[c + 3][r] = v.w;
            }
            __syncthreads();

#pragma unroll
            for (int k = 0; k < BKD; k++) {
                float a[TM], b[TN];
#pragma unroll
                for (int i = 0; i < TM; i += 4)
                    *reinterpret_cast<float4*>(&a[i]) =
                        *reinterpret_cast<const float4*>(&As[k][ty * TM + i]);
#pragma unroll
                for (int j = 0; j < TN; j += 4)
                    *reinterpret_cast<float4*>(&b[j]) =
                        *reinterpret_cast<const float4*>(&Bs[k][tx * TN + j]);
#pragma unroll
                for (int i = 0; i < TM; i++)
#pragma unroll
                    for (int j = 0; j < TN; j++)
                        acc[i][j] = fmaf(a[i], b[j], acc[i][j]);
            }
            __syncthreads();
        }

        // Epilogue for this code tile: fold into per-row running argmax.
        // score = dot^2 * inv_norm; argmax(score) == argmin(error).
#pragma unroll
        for (int j = 0; j < TN; j++) {
            int code = code0 + tx * TN + j;
            float invn = __ldg(&g_inv_norms[code]);
#pragma unroll
            for (int i = 0; i < TM; i++) {
                float d = acc[i][j];
                float s = d * d * invn;
                if (s > best_score[i]) {   // strict > keeps earliest index
                    best_score[i] = s;
                    best_idx[i] = code;
                    best_dot[i] = d;
                }
            }
        }
    }

    // Cross-thread reduction: 16 candidates per row (one per tx).
#pragma unroll
    for (int i = 0; i < TM; i++) {
        int r = ty * TM + i;
        s_score[r][tx] = best_score[i];
        s_bidx[r][tx]  = best_idx[i];
        s_bdot[r][tx]  = best_dot[i];
    }
    __syncthreads();

    if (tid < BM) {
        float bs = -1.0f; int bi = 0; float bd = 0.0f;
#pragma unroll
        for (int t = 0; t < 16; t++) {
            float sc = s_score[tid][t];
            int   ix = s_bidx[tid][t];
            if (sc > bs || (sc == bs && ix < bi)) {
                bs = sc; bi = ix; bd = s_bdot[tid][t];
            }
        }
        float alpha = bd * __ldg(&g_inv_norms[bi]);
        s_alpha[tid] = alpha;
        s_final[tid] = bi;
        if (write_idx) idx_out[row0 + tid] = (float)bi;
    }
    __syncthreads();

    // Write z = alpha * C[idx]: 256 threads, 4 rows per pass (64 float4/row).
#pragma unroll 4
    for (int p = 0; p < BM / 4; p++) {
        int r  = p * 4 + (tid >> 6);
        int d4 = tid & 63;
        float a = s_alpha[r];
        int   ci = s_final[r];
        float4 cv = __ldg(reinterpret_cast<const float4*>(C + (size_t)ci * D_SZ) + d4);
        float4 o = make_float4(a * cv.x, a * cv.y, a * cv.z, a * cv.w);
        *(reinterpret_cast<float4*>(z_out + (size_t)(row0 + r) * D_SZ) + d4) = o;
    }
}

// ---------------------------------------------------------------------------
extern "C" void kernel_launch(void* const* d_in, const int* in_sizes, int n_in,
                              void* d_out, int out_size) {
    const float* E = (const float*)d_in[0];   // embedding [B, D]
    const float* C = (const float*)d_in[1];   // codebook  [K, D]
    float* z = (float*)d_out;                 // z_out [B*D], then indices [B]
    float* idx = z + (size_t)B_SZ * D_SZ;
    int write_idx = (out_size >= B_SZ * D_SZ + B_SZ) ? 1 : 0;

    vq_norms_kernel<<<K_SZ, 32>>>(C);
    vq_main_kernel<<<B_SZ / BM, NTHREADS>>>(E, C, z, idx, write_idx);
}